// round 13
// baseline (speedup 1.0000x reference)
#include <cuda_runtime.h>
#include <cuda_bf16.h>
#include <cstdint>

// Embedding gather: out[r, :] = table[indices[r], :]
// n_rows = B*F = 819200, D = 64 floats (256 B per row).
//
// R12: disentangle R5. R5 = evict_last policy + 256-bit load shape and
// regressed; this tests the 256-bit shape ALONE (plain ld.global.nc.v8.b32,
// no residency hint): 8 lanes/row x 32 B/lane -> half the load instructions
// and half the L2 requests per row. Stores remain the proven 16B .cs
// streaming pattern. Everything else is the converged R11 config.

static constexpr int D      = 64;           // embedding dim (floats)
static constexpr int LANES  = 8;            // 32 B per lane
static constexpr int RPT    = 4;            // rows per thread
static constexpr int BLOCK  = 512;
static constexpr int GROUPS = BLOCK / LANES;              // 64 row-groups
static constexpr int ROWS_PER_BLOCK = GROUPS * RPT;       // 256

struct V8 { float4 a, b; };

__device__ __forceinline__ V8 ldg_32B(const float* p)
{
    V8 v;
    asm volatile("ld.global.nc.v8.b32 {%0,%1,%2,%3,%4,%5,%6,%7}, [%8];"
                 : "=f"(v.a.x), "=f"(v.a.y), "=f"(v.a.z), "=f"(v.a.w),
                   "=f"(v.b.x), "=f"(v.b.y), "=f"(v.b.z), "=f"(v.b.w)
                 : "l"(p));
    return v;
}

__global__ __launch_bounds__(BLOCK)
void gather_main(const int* __restrict__ indices,
                 const float* __restrict__ table,
                 float* __restrict__ out)
{
    const unsigned local_row = threadIdx.x >> 3;   // 0..63
    const unsigned lane      = threadIdx.x & 7u;   // 0..7
    const unsigned row_base  = blockIdx.x * (unsigned)ROWS_PER_BLOCK + local_row;

    unsigned idx[RPT];
    V8       vals[RPT];

    // Phase 1: batched independent index loads
#pragma unroll
    for (int k = 0; k < RPT; k++)
        idx[k] = (unsigned)__ldg(indices + row_base + k * GROUPS);

    // Phase 2: batched independent 32B table gathers (MLP = RPT)
#pragma unroll
    for (int k = 0; k < RPT; k++)
        vals[k] = ldg_32B(table + idx[k] * (unsigned)D + lane * 8u);

    // Phase 3: streaming stores (evict-first; output is write-once)
#pragma unroll
    for (int k = 0; k < RPT; k++) {
        float4* dst = reinterpret_cast<float4*>(
            out + (row_base + k * GROUPS) * (unsigned)D) + lane * 2u;
        __stcs(dst,     vals[k].a);
        __stcs(dst + 1, vals[k].b);
    }
}

__global__ __launch_bounds__(BLOCK)
void gather_tail(const int* __restrict__ indices,
                 const float* __restrict__ table,
                 float* __restrict__ out,
                 unsigned row_start, unsigned n_rows)
{
    const unsigned row  = row_start + blockIdx.x * GROUPS + (threadIdx.x >> 3);
    const unsigned lane = threadIdx.x & 7u;
    if (row >= n_rows) return;
    const unsigned idx = (unsigned)__ldg(indices + row);
    const V8 v = ldg_32B(table + idx * (unsigned)D + lane * 8u);
    float4* dst = reinterpret_cast<float4*>(out + row * (unsigned)D) + lane * 2u;
    __stcs(dst,     v.a);
    __stcs(dst + 1, v.b);
}

extern "C" void kernel_launch(void* const* d_in, const int* in_sizes, int n_in,
                              void* d_out, int out_size)
{
    const int*   indices = (const int*)d_in[0];
    const float* table   = (const float*)d_in[1];
    float*       out     = (float*)d_out;

    const unsigned n_rows    = (unsigned)in_sizes[0];          // 819200
    const unsigned full_blks = n_rows / ROWS_PER_BLOCK;        // 3200 (exact)
    const unsigned done      = full_blks * ROWS_PER_BLOCK;

    if (full_blks)
        gather_main<<<full_blks, BLOCK>>>(indices, table, out);

    if (done < n_rows) {
        const unsigned rem  = n_rows - done;
        const unsigned blks = (rem * LANES + BLOCK - 1) / BLOCK;
        gather_tail<<<blks, BLOCK>>>(indices, table, out, done, n_rows);
    }
}

// round 14
// speedup vs baseline: 1.0398x; 1.0398x over previous
#include <cuda_runtime.h>
#include <cuda_bf16.h>
#include <cstdint>

// Embedding gather: out[r, :] = table[indices[r], :]
// n_rows = B*F = 819200, D = 64 floats (256 B per row).
//
// FINAL (= R11 config; best measured: bench 62.6us, kernel 57.4us,
// DRAM 73.6% SOL, HBM 5.83 TB/s).
//
// Convergence evidence across 13 variants: reg-MLP 1/4/8, cp.async burst,
// barrier-free cp.async pipeline, evict_last(+v8 shape), plain v8 shape,
// L1-bypass .cg, u32 addressing, BLOCK 256/512, persistent grid. All land
// 57.4-64us; traffic sits at the byte floor (~333 MB = 143 MB unique table
// reads + 210 MB streaming writes + 3 MB indices; L2 absorbs duplicates).
// ~73% DRAM SOL is this part's efficiency ceiling for interleaved random
// 256B gathers + streaming writes. Notable negative results:
//  - v8.b32 (32B/lane) loads REGRESS: each warp touches 32 scattered rows
//    per instruction -> 2x L1tex wavefronts, DRAM drops to 66%.
//  - evict_last cannot beat LRU (random reuse distance over 143 MB > L2).
//  - persistent grid loses block-level parallelism (bench 68us).
//
// Structure: 16 float4 lanes per row, RPT=8 front-batched independent
// gathers per thread, 512-thread CTAs, u32 address math, exact-tile
// main kernel (no predicates) + guarded tail, .cs streaming stores.

static constexpr int D      = 64;           // embedding dim (floats)
static constexpr int LANES  = 16;           // float4 lanes per row
static constexpr int RPT    = 8;            // rows per thread
static constexpr int BLOCK  = 512;
static constexpr int GROUPS = BLOCK / LANES;              // 32 row-groups
static constexpr int ROWS_PER_BLOCK = GROUPS * RPT;       // 256

__global__ __launch_bounds__(BLOCK)
void gather_main(const int* __restrict__ indices,
                 const float4* __restrict__ table4,
                 float4* __restrict__ out4)
{
    const unsigned local_row = threadIdx.x >> 4;   // 0..31
    const unsigned lane      = threadIdx.x & 15u;  // 0..15
    const unsigned row_base  = blockIdx.x * (unsigned)ROWS_PER_BLOCK + local_row;

    unsigned idx[RPT];
    float4   vals[RPT];

    // Phase 1: batched independent index loads (L1-broadcast across lanes)
#pragma unroll
    for (int k = 0; k < RPT; k++)
        idx[k] = (unsigned)__ldg(indices + row_base + k * GROUPS);

    // Phase 2: batched independent table gathers (MLP = RPT)
#pragma unroll
    for (int k = 0; k < RPT; k++)
        vals[k] = __ldg(table4 + idx[k] * (unsigned)(D / 4) + lane);

    // Phase 3: streaming stores (evict-first; output is write-once)
#pragma unroll
    for (int k = 0; k < RPT; k++)
        __stcs(out4 + (row_base + k * GROUPS) * (unsigned)(D / 4) + lane, vals[k]);
}

__global__ __launch_bounds__(BLOCK)
void gather_tail(const int* __restrict__ indices,
                 const float4* __restrict__ table4,
                 float4* __restrict__ out4,
                 unsigned row_start, unsigned n_rows)
{
    const unsigned row  = row_start + blockIdx.x * GROUPS + (threadIdx.x >> 4);
    const unsigned lane = threadIdx.x & 15u;
    if (row >= n_rows) return;
    const unsigned idx = (unsigned)__ldg(indices + row);
    __stcs(out4 + row * (unsigned)(D / 4) + lane,
           __ldg(table4 + idx * (unsigned)(D / 4) + lane));
}

extern "C" void kernel_launch(void* const* d_in, const int* in_sizes, int n_in,
                              void* d_out, int out_size)
{
    const int*    indices = (const int*)d_in[0];
    const float4* table4  = (const float4*)d_in[1];
    float4*       out4    = (float4*)d_out;

    const unsigned n_rows    = (unsigned)in_sizes[0];          // 819200
    const unsigned full_blks = n_rows / ROWS_PER_BLOCK;        // 3200 (exact)
    const unsigned done      = full_blks * ROWS_PER_BLOCK;

    if (full_blks)
        gather_main<<<full_blks, BLOCK>>>(indices, table4, out4);

    if (done < n_rows) {
        const unsigned rem  = n_rows - done;
        const unsigned blks = (rem * LANES + BLOCK - 1) / BLOCK;
        gather_tail<<<blks, BLOCK>>>(indices, table4, out4, done, n_rows);
    }
}

// round 15
// speedup vs baseline: 1.0424x; 1.0025x over previous
#include <cuda_runtime.h>
#include <cuda_bf16.h>
#include <cstdint>

// Embedding gather: out[r, :] = table[indices[r], :]
// n_rows = B*F = 819200, D = 64 floats (256 B per row).
//
// FINAL. Best measured: bench 62.6us, kernel 57.4us, DRAM 73.6% SOL,
// HBM 5.83 TB/s, traffic at the analytic byte floor (~333 MB).
//
// Converged across 13 structural variants over 14 rounds:
//  - MLP depth (1/4/8 reg-resident, cp.async burst, cp.async pipeline):
//    all >=4 equivalent; latency fully hidden.
//  - Load width: 16B/lane optimal. 32B/lane (v8.b32) regresses (2x L1tex
//    wavefronts per instruction, DRAM 73%->66%).
//  - L2 policy: evict_last loses to LRU (random reuse distance > L2).
//  - L1 bypass (.cg): neutral.
//  - Launch shape: BLOCK=512 one-shot best; persistent grid regresses.
// => ~73% DRAM SOL is the sm_103a efficiency ceiling for interleaved
//    random-256B gathers + streaming writes. Nothing else binds.
//
// Structure: 16 float4 lanes per row, RPT=8 front-batched independent
// gathers per thread, 512-thread CTAs, u32 address math, exact-tile
// main kernel (no predicates) + guarded tail, .cs streaming stores.

static constexpr int D      = 64;           // embedding dim (floats)
static constexpr int LANES  = 16;           // float4 lanes per row
static constexpr int RPT    = 8;            // rows per thread
static constexpr int BLOCK  = 512;
static constexpr int GROUPS = BLOCK / LANES;              // 32 row-groups
static constexpr int ROWS_PER_BLOCK = GROUPS * RPT;       // 256

__global__ __launch_bounds__(BLOCK)
void gather_main(const int* __restrict__ indices,
                 const float4* __restrict__ table4,
                 float4* __restrict__ out4)
{
    const unsigned local_row = threadIdx.x >> 4;   // 0..31
    const unsigned lane      = threadIdx.x & 15u;  // 0..15
    const unsigned row_base  = blockIdx.x * (unsigned)ROWS_PER_BLOCK + local_row;

    unsigned idx[RPT];
    float4   vals[RPT];

    // Phase 1: batched independent index loads (L1-broadcast across lanes)
#pragma unroll
    for (int k = 0; k < RPT; k++)
        idx[k] = (unsigned)__ldg(indices + row_base + k * GROUPS);

    // Phase 2: batched independent table gathers (MLP = RPT)
#pragma unroll
    for (int k = 0; k < RPT; k++)
        vals[k] = __ldg(table4 + idx[k] * (unsigned)(D / 4) + lane);

    // Phase 3: streaming stores (evict-first; output is write-once)
#pragma unroll
    for (int k = 0; k < RPT; k++)
        __stcs(out4 + (row_base + k * GROUPS) * (unsigned)(D / 4) + lane, vals[k]);
}

__global__ __launch_bounds__(BLOCK)
void gather_tail(const int* __restrict__ indices,
                 const float4* __restrict__ table4,
                 float4* __restrict__ out4,
                 unsigned row_start, unsigned n_rows)
{
    const unsigned row  = row_start + blockIdx.x * GROUPS + (threadIdx.x >> 4);
    const unsigned lane = threadIdx.x & 15u;
    if (row >= n_rows) return;
    const unsigned idx = (unsigned)__ldg(indices + row);
    __stcs(out4 + row * (unsigned)(D / 4) + lane,
           __ldg(table4 + idx * (unsigned)(D / 4) + lane));
}

extern "C" void kernel_launch(void* const* d_in, const int* in_sizes, int n_in,
                              void* d_out, int out_size)
{
    const int*    indices = (const int*)d_in[0];
    const float4* table4  = (const float4*)d_in[1];
    float4*       out4    = (float4*)d_out;

    const unsigned n_rows    = (unsigned)in_sizes[0];          // 819200
    const unsigned full_blks = n_rows / ROWS_PER_BLOCK;        // 3200 (exact)
    const unsigned done      = full_blks * ROWS_PER_BLOCK;

    if (full_blks)
        gather_main<<<full_blks, BLOCK>>>(indices, table4, out4);

    if (done < n_rows) {
        const unsigned rem  = n_rows - done;
        const unsigned blks = (rem * LANES + BLOCK - 1) / BLOCK;
        gather_tail<<<blks, BLOCK>>>(indices, table4, out4, done, n_rows);
    }
}